// round 15
// baseline (speedup 1.0000x reference)
#include <cuda_runtime.h>
#include <cuda_fp16.h>
#include <stdint.h>

// ---------------- problem constants ----------------
#define NNODES 50000
#define NEDGES 1000000
#define HID    128
#define THREADS 512
#define WPB    16
#define GROUPS (NEDGES / 16)   // 62500, exact

// ---------------- main-kernel smem layout ----------------
#define S_STRIDE  272
#define SOFF_S    0                           // 16*16*272 = 69632
#define EA_STRIDE 48
#define SOFF_EA   69632                       // 12288 -> 81920
#define W1C_STRIDE 48
#define SOFF_W1C  81920                       // 6144 -> 88064
#define W2T_STRIDE 272
#define SOFF_W2T  88064                       // 2176 -> 90240
#define SMEM_MAIN 90240

// ---------------- prep_P smem layout ----------------
#define PP_BSTR    272
#define PP_SOFF_BA 0
#define PP_SOFF_BB 34816
#define PP_SOFF_AS 69632
#define PP_SOFF_B1 139264
#define PP_SMEM    139776
#define PP_TILES   3125                       // one job per 16-node tile (both mats)

// ---------------- device globals ----------------
__device__ __half g_P1[(size_t)NNODES * HID];     // feat @ W1a^T + b1 (fp16)
__device__ __half g_P2[(size_t)NNODES * HID];     // feat @ W1b^T      (fp16)
__device__ __half g_W1ab[2 * 128 * 128];          // [m][n][k] fp16
__device__ __half g_W1cT[128 * 16];               // [n][k] ea weights
__device__ __half g_W2T[8 * 128];                 // [n(pad8)][k] W2 transposed
__device__ float  g_W1d[128];                     // dist weights
__device__ float  g_cnt[NNODES];

static __device__ __forceinline__ uint32_t smem_u32(const void* p) {
    uint32_t a;
    asm("{ .reg .u64 t; cvta.to.shared.u64 t, %1; cvt.u32.u64 %0, t; }" : "=r"(a) : "l"(p));
    return a;
}
static __device__ __forceinline__ float silu(float x) { return x / (1.f + __expf(-x)); }
static __device__ __forceinline__ uint32_t silu_h2(uint32_t x) {
    uint32_t a, t, r;
    asm("mul.rn.f16x2 %0, %1, %2;" : "=r"(a) : "r"(x), "r"(0x38003800u));
    asm("tanh.approx.f16x2 %0, %1;" : "=r"(t) : "r"(a));
    asm("fma.rn.f16x2 %0, %1, %2, %3;" : "=r"(r) : "r"(a), "r"(t), "r"(a));
    return r;
}

#define LDSM_X4(r0,r1,r2,r3,addr) \
    asm volatile("ldmatrix.sync.aligned.m8n8.x4.shared.b16 {%0,%1,%2,%3}, [%4];" \
                 : "=r"(r0), "=r"(r1), "=r"(r2), "=r"(r3) : "r"(addr))
#define MMA16816(d0,d1,d2,d3,a0,a1,a2,a3,b0,b1) \
    asm volatile("mma.sync.aligned.m16n8k16.row.col.f32.f16.f16.f32 " \
                 "{%0,%1,%2,%3}, {%4,%5,%6,%7}, {%8,%9}, {%0,%1,%2,%3};" \
                 : "+f"(d0), "+f"(d1), "+f"(d2), "+f"(d3) \
                 : "r"(a0), "r"(a1), "r"(a2), "r"(a3), "r"(b0), "r"(b1))

// ---------------- init: zero + weight repack ----------------
// msg order: [0]=dist, [1..128]=feat_row, [129..256]=feat_col, [257..272]=ea
__global__ void init_kernel(float* __restrict__ out,
                            const float* __restrict__ W1,
                            const float* __restrict__ W2) {
    int idx = blockIdx.x * blockDim.x + threadIdx.x;
    int stride = gridDim.x * blockDim.x;
    for (int j = idx; j < NNODES * 9; j += stride) out[j] = 0.f;
    for (int j = idx; j < NNODES; j += stride) g_cnt[j] = 0.f;
    if (idx < 32768) {
        int m = idx >> 14, n = (idx >> 7) & 127, k = idx & 127;
        g_W1ab[idx] = __float2half(W1[(1 + m * 128 + k) * HID + n]);
    } else if (idx < 34816) {
        int j = idx - 32768; int n = j >> 4, c = j & 15;
        g_W1cT[j] = __float2half(W1[(257 + c) * HID + n]);
    } else if (idx < 35840) {
        int j = idx - 34816; int nr = j >> 7, k = j & 127;
        g_W2T[j] = __float2half(nr < 3 ? W2[k * 3 + nr] : 0.f);
    } else if (idx < 35968) {
        int j = idx - 35840;
        g_W1d[j] = W1[j];
    }
}

__global__ void finalize_kernel(float* __restrict__ out) {
    int j = blockIdx.x * blockDim.x + threadIdx.x;
    if (j < NNODES * 9)
        out[j] = out[j] / fmaxf(g_cnt[j / 9], 1.0f);
}

// ---------------- P precompute: ONE job per tile, both mats reuse staged A ----------------
__global__ void __launch_bounds__(512, 1)
prep_P_kernel(const float* __restrict__ nf, const float* __restrict__ b1) {
    extern __shared__ char sm[];
    const uint32_t smb = smem_u32(sm);
    int tid = threadIdx.x, wid = tid >> 5, lid = tid & 31;

    {
        const uint4* srcA = (const uint4*)g_W1ab;
        const uint4* srcB = (const uint4*)(g_W1ab + 16384);
        for (int i = tid; i < 2048; i += 512) {
            int row = i >> 4, p = i & 15;
            *(uint4*)(sm + PP_SOFF_BA + row * PP_BSTR + p * 16) = srcA[i];
            *(uint4*)(sm + PP_SOFF_BB + row * PP_BSTR + p * 16) = srcB[i];
        }
        float* b1sw = (float*)(sm + PP_SOFF_B1);
        if (tid < HID) b1sw[tid] = b1[tid];
    }
    __syncthreads();
    const float* b1s = (const float*)(sm + PP_SOFF_B1);

    char* Aw = sm + PP_SOFF_AS + wid * 16 * PP_BSTR;
    const uint32_t aBase = smb + PP_SOFF_AS + (uint32_t)wid * 16 * PP_BSTR
                         + (uint32_t)((lid & 7) + ((lid >> 3) & 1) * 8) * PP_BSTR
                         + ((lid >> 4) & 1) * 16;
    const uint32_t bRowOff = (uint32_t)((lid & 7) + ((lid >> 4) & 1) * 8) * PP_BSTR
                           + ((lid >> 3) & 1) * 16;
    const int gq = lid >> 2, tq = lid & 3;

    const int jstride = gridDim.x * 16;
    for (int tile = blockIdx.x * 16 + wid; tile < PP_TILES; tile += jstride) {
        const int node0 = tile * 16;

        // stage A once (all 16 rows' loads in flight)
        {
            float4 v[16];
            #pragma unroll
            for (int i = 0; i < 16; ++i)
                v[i] = *(const float4*)(nf + (size_t)(node0 + i) * HID + 4 * lid);
            #pragma unroll
            for (int i = 0; i < 16; ++i) {
                __half2 h0 = __floats2half2_rn(v[i].x, v[i].y);
                __half2 h1 = __floats2half2_rn(v[i].z, v[i].w);
                uint2 pk; pk.x = *(uint32_t*)&h0; pk.y = *(uint32_t*)&h1;
                *(uint2*)(Aw + i * PP_BSTR + lid * 8) = pk;
            }
        }
        __syncwarp();

        // both matmuls reuse the staged A tile
        #pragma unroll 1
        for (int mat = 0; mat < 2; ++mat) {
            uint32_t bBase = smb + (mat ? PP_SOFF_BB : PP_SOFF_BA) + bRowOff;
            __half* OUT = mat ? g_P2 : g_P1;
            float acc[16][4];
            #pragma unroll
            for (int nt = 0; nt < 16; ++nt) { acc[nt][0]=0.f; acc[nt][1]=0.f; acc[nt][2]=0.f; acc[nt][3]=0.f; }
            #pragma unroll 1
            for (int ks = 0; ks < 8; ++ks) {
                uint32_t a0,a1,a2,a3;
                LDSM_X4(a0,a1,a2,a3, aBase + ks * 32);
                #pragma unroll
                for (int j = 0; j < 8; ++j) {
                    uint32_t b0,b1r,b2,b3;
                    LDSM_X4(b0,b1r,b2,b3, bBase + (uint32_t)j * 16 * PP_BSTR + ks * 32);
                    MMA16816(acc[2*j][0],acc[2*j][1],acc[2*j][2],acc[2*j][3], a0,a1,a2,a3, b0,b1r);
                    MMA16816(acc[2*j+1][0],acc[2*j+1][1],acc[2*j+1][2],acc[2*j+1][3], a0,a1,a2,a3, b2,b3);
                }
            }
            #pragma unroll
            for (int nt = 0; nt < 16; ++nt) {
                int col = nt * 8 + tq * 2;
                float bx = 0.f, by = 0.f;
                if (mat == 0) { bx = b1s[col]; by = b1s[col + 1]; }
                __half2 v0 = __floats2half2_rn(acc[nt][0] + bx, acc[nt][1] + by);
                __half2 v1 = __floats2half2_rn(acc[nt][2] + bx, acc[nt][3] + by);
                *(__half2*)(OUT + (size_t)(node0 + gq)     * HID + col) = v0;
                *(__half2*)(OUT + (size_t)(node0 + gq + 8) * HID + col) = v1;
            }
        }
        __syncwarp();
    }
}

// ---------------- main edge kernel (champion hot loop) ----------------
__global__ void __launch_bounds__(THREADS, 1)
edge_kernel(const float* __restrict__ pos,
            const float* __restrict__ edge_attr,
            const float* __restrict__ b2,
            const int*   __restrict__ ei,
            float*       __restrict__ out)
{
    extern __shared__ char sm[];
    const uint32_t smb = smem_u32(sm);
    const int tid = threadIdx.x, wid = tid >> 5, lid = tid & 31;

    for (int i = tid; i < 256; i += THREADS) {
        int row = i >> 1, p = i & 1;
        *(uint4*)(sm + SOFF_W1C + row * W1C_STRIDE + p * 16) = ((const uint4*)g_W1cT)[i];
    }
    for (int i = tid; i < 128; i += THREADS) {
        int row = i >> 4, p = i & 15;
        *(uint4*)(sm + SOFF_W2T + row * W2T_STRIDE + p * 16) = ((const uint4*)g_W2T)[i];
    }
    const __half2 w1dA = __floats2half2_rn(g_W1d[4*lid],     g_W1d[4*lid + 1]);
    const __half2 w1dB = __floats2half2_rn(g_W1d[4*lid + 2], g_W1d[4*lid + 3]);
    const float b20 = b2[0], b21 = b2[1], b22 = b2[2];
    __syncthreads();

    uint32_t b2f[8][2];
    {
        uint32_t addr = smb + SOFF_W2T + (uint32_t)(lid & 7) * W2T_STRIDE + ((lid >> 3) & 1) * 16;
        #pragma unroll
        for (int s = 0; s < 8; ++s)
            asm volatile("ldmatrix.sync.aligned.m8n8.x2.shared.b16 {%0,%1}, [%2];"
                         : "=r"(b2f[s][0]), "=r"(b2f[s][1]) : "r"(addr + s * 32));
    }

    char* Sw  = sm + SOFF_S  + (size_t)wid * 16 * S_STRIDE;
    char* eaW = sm + SOFF_EA + (size_t)wid * 16 * EA_STRIDE;
    const uint32_t eaU = smb + SOFF_EA + (uint32_t)wid * 16 * EA_STRIDE;
    const int gq = lid >> 2, t4 = (lid & 3) * 2;
    const uint32_t aAddr = eaU + (uint32_t)((lid & 7) + ((lid >> 3) & 1) * 8) * EA_STRIDE
                         + ((lid >> 4) & 1) * 16;
    const uint32_t b1Off = smb + SOFF_W1C
                         + (uint32_t)((lid & 7) + ((lid >> 4) & 1) * 8) * W1C_STRIDE
                         + ((lid >> 3) & 1) * 16;

    for (int g = blockIdx.x * WPB + wid; g < GROUPS; g += gridDim.x * WPB) {
        const int e0 = g * 16;

        int r = 0, c = 0;
        float dx = 0.f, dy = 0.f, dz = 0.f, dd = 0.f;
        if (lid < 16) {
            r = ei[e0 + lid];
            c = ei[NEDGES + e0 + lid];
            dx = pos[3*r+0] - pos[3*c+0];
            dy = pos[3*r+1] - pos[3*c+1];
            dz = pos[3*r+2] - pos[3*c+2];
            dd = sqrtf(dx*dx + dy*dy + dz*dz);
        }
        __syncwarp();

        // ---- S build: single 16-row batch ----
        {
            uint2 p1v[16], p2v[16];
            #pragma unroll
            for (int i = 0; i < 16; ++i) {
                int ri = __shfl_sync(0xffffffffu, r, i);
                int ci = __shfl_sync(0xffffffffu, c, i);
                p1v[i] = *(const uint2*)(g_P1 + (size_t)ri * HID + 4 * lid);
                p2v[i] = *(const uint2*)(g_P2 + (size_t)ci * HID + 4 * lid);
            }
            #pragma unroll
            for (int i = 0; i < 16; ++i) {
                float di = __shfl_sync(0xffffffffu, dd, i);
                __half2 dh = __float2half2_rn(di);
                __half2 sa = __hfma2(dh, w1dA, __hadd2(*(__half2*)&p1v[i].x, *(__half2*)&p2v[i].x));
                __half2 sb = __hfma2(dh, w1dB, __hadd2(*(__half2*)&p1v[i].y, *(__half2*)&p2v[i].y));
                uint2 pk;
                pk.x = *(uint32_t*)&sa; pk.y = *(uint32_t*)&sb;
                *(uint2*)(Sw + i * S_STRIDE + 8 * lid) = pk;
            }
        }
        {
            int erow = lid >> 1, hb = lid & 1;
            const float4* src = (const float4*)(edge_attr + (size_t)(e0 + erow) * 16 + hb * 8);
            float4 u0 = src[0], u1 = src[1];
            __half2 h0 = __floats2half2_rn(u0.x, u0.y), h1 = __floats2half2_rn(u0.z, u0.w);
            __half2 h2 = __floats2half2_rn(u1.x, u1.y), h3 = __floats2half2_rn(u1.z, u1.w);
            uint4 pk;
            pk.x = *(uint32_t*)&h0; pk.y = *(uint32_t*)&h1;
            pk.z = *(uint32_t*)&h2; pk.w = *(uint32_t*)&h3;
            *(uint4*)(eaW + erow * EA_STRIDE + hb * 16) = pk;
        }
        __syncwarp();

        uint32_t a0, a1, a2, a3;
        LDSM_X4(a0, a1, a2, a3, aAddr);

        float acc2[4] = {0.f, 0.f, 0.f, 0.f};
        #pragma unroll
        for (int half = 0; half < 2; ++half) {
            uint32_t bb[4][4];
            #pragma unroll
            for (int j = 0; j < 4; ++j)
                LDSM_X4(bb[j][0], bb[j][1], bb[j][2], bb[j][3],
                        b1Off + (uint32_t)(half * 64 + j * 16) * W1C_STRIDE);
            float acc1[8][4];
            #pragma unroll
            for (int nt = 0; nt < 8; ++nt) { acc1[nt][0]=0.f; acc1[nt][1]=0.f; acc1[nt][2]=0.f; acc1[nt][3]=0.f; }
            #pragma unroll
            for (int j = 0; j < 4; ++j) {
                MMA16816(acc1[2*j][0],acc1[2*j][1],acc1[2*j][2],acc1[2*j][3], a0,a1,a2,a3, bb[j][0], bb[j][1]);
                MMA16816(acc1[2*j+1][0],acc1[2*j+1][1],acc1[2*j+1][2],acc1[2*j+1][3], a0,a1,a2,a3, bb[j][2], bb[j][3]);
            }
            uint32_t hA[8], hB[8];
            #pragma unroll
            for (int nt = 0; nt < 8; ++nt) {
                int colb = (half * 64 + nt * 8 + t4) * 2;
                uint32_t s0 = *(const uint32_t*)(Sw + gq * S_STRIDE + colb);
                uint32_t s1 = *(const uint32_t*)(Sw + (gq + 8) * S_STRIDE + colb);
                __half2 e0h = __floats2half2_rn(acc1[nt][0], acc1[nt][1]);
                __half2 e1h = __floats2half2_rn(acc1[nt][2], acc1[nt][3]);
                __half2 pre0 = __hadd2(e0h, *(__half2*)&s0);
                __half2 pre1 = __hadd2(e1h, *(__half2*)&s1);
                hA[nt] = silu_h2(*(uint32_t*)&pre0);
                hB[nt] = silu_h2(*(uint32_t*)&pre1);
            }
            #pragma unroll
            for (int s2 = 0; s2 < 4; ++s2) {
                int s = half * 4 + s2;
                MMA16816(acc2[0], acc2[1], acc2[2], acc2[3],
                         hA[2*s2], hB[2*s2], hA[2*s2+1], hB[2*s2+1],
                         b2f[s][0], b2f[s][1]);
            }
        }

        int m4 = (lid & 7) * 4;
        float q0 = __shfl_sync(0xffffffffu, acc2[0], m4);
        float q1 = __shfl_sync(0xffffffffu, acc2[1], m4);
        float q2 = __shfl_sync(0xffffffffu, acc2[2], m4);
        float q3 = __shfl_sync(0xffffffffu, acc2[3], m4);
        float r0 = __shfl_sync(0xffffffffu, acc2[0], m4 + 1);
        float r2 = __shfl_sync(0xffffffffu, acc2[2], m4 + 1);
        if (lid < 16) {
            float pw0 = (lid < 8) ? q0 : q2;
            float pw1 = (lid < 8) ? q1 : q3;
            float pw2 = (lid < 8) ? r0 : r2;
            float w0  = silu(pw0 + b20);
            float w1v = silu(pw1 + b21);
            float w2v = silu(pw2 + b22);
            float inv = 1.f / fmaxf(dd, 1e-12f);
            float x = dx * inv, y = dy * inv, z = dz * inv;
            const float s3 = 1.7320508075688772f;
            float* o = out + (size_t)r * 9;
            atomicAdd(o + 0, w0);
            atomicAdd(o + 1, x * w1v);
            atomicAdd(o + 2, y * w1v);
            atomicAdd(o + 3, z * w1v);
            atomicAdd(o + 4, s3 * x * z * w2v);
            atomicAdd(o + 5, s3 * x * y * w2v);
            atomicAdd(o + 6, (y * y - 0.5f * (x * x + z * z)) * w2v);
            atomicAdd(o + 7, s3 * y * z * w2v);
            atomicAdd(o + 8, 0.5f * s3 * (z * z - x * x) * w2v);
            atomicAdd(&g_cnt[r], 1.0f);
        }
    }
}

// ---------------- launch ----------------
extern "C" void kernel_launch(void* const* d_in, const int* in_sizes, int n_in,
                              void* d_out, int out_size) {
    const float* node_feat = (const float*)d_in[0];
    const float* node_pos  = (const float*)d_in[1];
    const float* edge_attr = (const float*)d_in[2];
    const float* W1        = (const float*)d_in[3];
    const float* b1        = (const float*)d_in[4];
    const float* W2        = (const float*)d_in[5];
    const float* b2        = (const float*)d_in[6];
    const int*   ei        = (const int*)d_in[7];
    float* out = (float*)d_out;

    cudaFuncSetAttribute(prep_P_kernel, cudaFuncAttributeMaxDynamicSharedMemorySize, PP_SMEM);
    cudaFuncSetAttribute(edge_kernel,   cudaFuncAttributeMaxDynamicSharedMemorySize, SMEM_MAIN);

    init_kernel<<<512, 256>>>(out, W1, W2);
    prep_P_kernel<<<152, 512, PP_SMEM>>>(node_feat, b1);
    edge_kernel<<<152, THREADS, SMEM_MAIN>>>(node_pos, edge_attr, b2, ei, out);
    finalize_kernel<<<(NNODES * 9 + 255) / 256, 256>>>(out);
}

// round 16
// speedup vs baseline: 1.1633x; 1.1633x over previous
#include <cuda_runtime.h>
#include <cuda_fp16.h>
#include <stdint.h>

// ---------------- problem constants ----------------
#define NNODES 50000
#define NEDGES 1000000
#define HID    128
#define THREADS 512
#define WPB    16
#define GROUPS (NEDGES / 16)   // 62500, exact

// ---------------- main-kernel smem layout ----------------
#define S_STRIDE  272
#define SOFF_S    0                           // 16*16*272 = 69632
#define EA_STRIDE 48
#define SOFF_EA   69632                       // 12288 -> 81920
#define W1C_STRIDE 48
#define SOFF_W1C  81920                       // 6144 -> 88064
#define W2T_STRIDE 272
#define SOFF_W2T  88064                       // 2176 -> 90240
#define SMEM_MAIN 90240

// ---------------- prep_P smem layout ----------------
#define PP_BSTR    272
#define PP_SOFF_BA 0
#define PP_SOFF_BB 34816
#define PP_SOFF_AS 69632
#define PP_SOFF_B1 139264
#define PP_SMEM    139776
#define PP_JOBS    6250

// ---------------- device globals ----------------
__device__ __half g_P1[(size_t)NNODES * HID];     // feat @ W1a^T + b1 (fp16)
__device__ __half g_P2[(size_t)NNODES * HID];     // feat @ W1b^T      (fp16)
__device__ __half g_W1ab[2 * 128 * 128];          // [m][n][k] fp16
__device__ __half g_W1cT[128 * 16];               // [n][k] ea weights
__device__ __half g_W2T[8 * 128];                 // [n(pad8)][k] W2 transposed
__device__ float  g_W1d[128];                     // dist weights
__device__ float  g_acc[(size_t)NNODES * 12];     // [sh0..sh8, cnt, pad, pad] per node

static __device__ __forceinline__ uint32_t smem_u32(const void* p) {
    uint32_t a;
    asm("{ .reg .u64 t; cvta.to.shared.u64 t, %1; cvt.u32.u64 %0, t; }" : "=r"(a) : "l"(p));
    return a;
}
static __device__ __forceinline__ float silu(float x) { return x / (1.f + __expf(-x)); }
static __device__ __forceinline__ uint32_t silu_h2(uint32_t x) {
    uint32_t a, t, r;
    asm("mul.rn.f16x2 %0, %1, %2;" : "=r"(a) : "r"(x), "r"(0x38003800u));
    asm("tanh.approx.f16x2 %0, %1;" : "=r"(t) : "r"(a));
    asm("fma.rn.f16x2 %0, %1, %2, %3;" : "=r"(r) : "r"(a), "r"(t), "r"(a));
    return r;
}
// vectorized f32 reduction: one L2 atomic op covering 4 floats
#define RED4(p, a, b, c, d) \
    asm volatile("red.global.add.v4.f32 [%0], {%1, %2, %3, %4};" \
                 :: "l"(p), "f"(a), "f"(b), "f"(c), "f"(d) : "memory")

#define LDSM_X4(r0,r1,r2,r3,addr) \
    asm volatile("ldmatrix.sync.aligned.m8n8.x4.shared.b16 {%0,%1,%2,%3}, [%4];" \
                 : "=r"(r0), "=r"(r1), "=r"(r2), "=r"(r3) : "r"(addr))
#define MMA16816(d0,d1,d2,d3,a0,a1,a2,a3,b0,b1) \
    asm volatile("mma.sync.aligned.m16n8k16.row.col.f32.f16.f16.f32 " \
                 "{%0,%1,%2,%3}, {%4,%5,%6,%7}, {%8,%9}, {%0,%1,%2,%3};" \
                 : "+f"(d0), "+f"(d1), "+f"(d2), "+f"(d3) \
                 : "r"(a0), "r"(a1), "r"(a2), "r"(a3), "r"(b0), "r"(b1))

// ---------------- init: zero scratch + weight repack ----------------
// msg order: [0]=dist, [1..128]=feat_row, [129..256]=feat_col, [257..272]=ea
__global__ void init_kernel(const float* __restrict__ W1,
                            const float* __restrict__ W2) {
    int idx = blockIdx.x * blockDim.x + threadIdx.x;
    int stride = gridDim.x * blockDim.x;
    for (int j = idx; j < NNODES * 12; j += stride) g_acc[j] = 0.f;
    if (idx < 32768) {
        int m = idx >> 14, n = (idx >> 7) & 127, k = idx & 127;
        g_W1ab[idx] = __float2half(W1[(1 + m * 128 + k) * HID + n]);
    } else if (idx < 34816) {
        int j = idx - 32768; int n = j >> 4, c = j & 15;
        g_W1cT[j] = __float2half(W1[(257 + c) * HID + n]);
    } else if (idx < 35840) {
        int j = idx - 34816; int nr = j >> 7, k = j & 127;
        g_W2T[j] = __float2half(nr < 3 ? W2[k * 3 + nr] : 0.f);
    } else if (idx < 35968) {
        int j = idx - 35840;
        g_W1d[j] = W1[j];
    }
}

// per node: read 12-float scratch row, divide by cnt, write 9 outputs
__global__ void finalize_kernel(float* __restrict__ out) {
    int n = blockIdx.x * blockDim.x + threadIdx.x;
    if (n >= NNODES) return;
    const float4* a = (const float4*)(g_acc + (size_t)n * 12);
    float4 v0 = a[0], v1 = a[1], v2 = a[2];
    float inv = 1.f / fmaxf(v2.y, 1.0f);     // cnt in lane 9
    float* o = out + (size_t)n * 9;
    o[0] = v0.x * inv; o[1] = v0.y * inv; o[2] = v0.z * inv; o[3] = v0.w * inv;
    o[4] = v1.x * inv; o[5] = v1.y * inv; o[6] = v1.z * inv; o[7] = v1.w * inv;
    o[8] = v2.x * inv;
}

// ---------------- P precompute (persistent, job = (tile, mat)) — R13 form ----------------
__global__ void __launch_bounds__(512, 1)
prep_P_kernel(const float* __restrict__ nf, const float* __restrict__ b1) {
    extern __shared__ char sm[];
    const uint32_t smb = smem_u32(sm);
    int tid = threadIdx.x, wid = tid >> 5, lid = tid & 31;

    {
        const uint4* srcA = (const uint4*)g_W1ab;
        const uint4* srcB = (const uint4*)(g_W1ab + 16384);
        for (int i = tid; i < 2048; i += 512) {
            int row = i >> 4, p = i & 15;
            *(uint4*)(sm + PP_SOFF_BA + row * PP_BSTR + p * 16) = srcA[i];
            *(uint4*)(sm + PP_SOFF_BB + row * PP_BSTR + p * 16) = srcB[i];
        }
        float* b1sw = (float*)(sm + PP_SOFF_B1);
        if (tid < HID) b1sw[tid] = b1[tid];
    }
    __syncthreads();
    const float* b1s = (const float*)(sm + PP_SOFF_B1);

    char* Aw = sm + PP_SOFF_AS + wid * 16 * PP_BSTR;
    const uint32_t aBase = smb + PP_SOFF_AS + (uint32_t)wid * 16 * PP_BSTR
                         + (uint32_t)((lid & 7) + ((lid >> 3) & 1) * 8) * PP_BSTR
                         + ((lid >> 4) & 1) * 16;
    const uint32_t bRowOff = (uint32_t)((lid & 7) + ((lid >> 4) & 1) * 8) * PP_BSTR
                           + ((lid >> 3) & 1) * 16;
    const int gq = lid >> 2, tq = lid & 3;

    const int jstride = gridDim.x * 16;
    for (int job = blockIdx.x * 16 + wid; job < PP_JOBS; job += jstride) {
        const int tile = job >> 1, mat = job & 1;
        const int node0 = tile * 16;

        {
            float4 v[16];
            #pragma unroll
            for (int i = 0; i < 16; ++i)
                v[i] = *(const float4*)(nf + (size_t)(node0 + i) * HID + 4 * lid);
            #pragma unroll
            for (int i = 0; i < 16; ++i) {
                __half2 h0 = __floats2half2_rn(v[i].x, v[i].y);
                __half2 h1 = __floats2half2_rn(v[i].z, v[i].w);
                uint2 pk; pk.x = *(uint32_t*)&h0; pk.y = *(uint32_t*)&h1;
                *(uint2*)(Aw + i * PP_BSTR + lid * 8) = pk;
            }
        }
        __syncwarp();

        uint32_t bBase = smb + (mat ? PP_SOFF_BB : PP_SOFF_BA) + bRowOff;
        __half* OUT = mat ? g_P2 : g_P1;
        float acc[16][4];
        #pragma unroll
        for (int nt = 0; nt < 16; ++nt) { acc[nt][0]=0.f; acc[nt][1]=0.f; acc[nt][2]=0.f; acc[nt][3]=0.f; }
        #pragma unroll 1
        for (int ks = 0; ks < 8; ++ks) {
            uint32_t a0,a1,a2,a3;
            LDSM_X4(a0,a1,a2,a3, aBase + ks * 32);
            #pragma unroll
            for (int j = 0; j < 8; ++j) {
                uint32_t b0,b1r,b2,b3;
                LDSM_X4(b0,b1r,b2,b3, bBase + (uint32_t)j * 16 * PP_BSTR + ks * 32);
                MMA16816(acc[2*j][0],acc[2*j][1],acc[2*j][2],acc[2*j][3], a0,a1,a2,a3, b0,b1r);
                MMA16816(acc[2*j+1][0],acc[2*j+1][1],acc[2*j+1][2],acc[2*j+1][3], a0,a1,a2,a3, b2,b3);
            }
        }
        #pragma unroll
        for (int nt = 0; nt < 16; ++nt) {
            int col = nt * 8 + tq * 2;
            float bx = 0.f, by = 0.f;
            if (mat == 0) { bx = b1s[col]; by = b1s[col + 1]; }
            __half2 v0 = __floats2half2_rn(acc[nt][0] + bx, acc[nt][1] + by);
            __half2 v1 = __floats2half2_rn(acc[nt][2] + bx, acc[nt][3] + by);
            *(__half2*)(OUT + (size_t)(node0 + gq)     * HID + col) = v0;
            *(__half2*)(OUT + (size_t)(node0 + gq + 8) * HID + col) = v1;
        }
        __syncwarp();
    }
}

// ---------------- main edge kernel (R13 champion hot loop; v4 reductions) ----------------
__global__ void __launch_bounds__(THREADS, 1)
edge_kernel(const float* __restrict__ pos,
            const float* __restrict__ edge_attr,
            const float* __restrict__ b2,
            const int*   __restrict__ ei)
{
    extern __shared__ char sm[];
    const uint32_t smb = smem_u32(sm);
    const int tid = threadIdx.x, wid = tid >> 5, lid = tid & 31;

    for (int i = tid; i < 256; i += THREADS) {
        int row = i >> 1, p = i & 1;
        *(uint4*)(sm + SOFF_W1C + row * W1C_STRIDE + p * 16) = ((const uint4*)g_W1cT)[i];
    }
    for (int i = tid; i < 128; i += THREADS) {
        int row = i >> 4, p = i & 15;
        *(uint4*)(sm + SOFF_W2T + row * W2T_STRIDE + p * 16) = ((const uint4*)g_W2T)[i];
    }
    const __half2 w1dA = __floats2half2_rn(g_W1d[4*lid],     g_W1d[4*lid + 1]);
    const __half2 w1dB = __floats2half2_rn(g_W1d[4*lid + 2], g_W1d[4*lid + 3]);
    const float b20 = b2[0], b21 = b2[1], b22 = b2[2];
    __syncthreads();

    uint32_t b2f[8][2];
    {
        uint32_t addr = smb + SOFF_W2T + (uint32_t)(lid & 7) * W2T_STRIDE + ((lid >> 3) & 1) * 16;
        #pragma unroll
        for (int s = 0; s < 8; ++s)
            asm volatile("ldmatrix.sync.aligned.m8n8.x2.shared.b16 {%0,%1}, [%2];"
                         : "=r"(b2f[s][0]), "=r"(b2f[s][1]) : "r"(addr + s * 32));
    }

    char* Sw  = sm + SOFF_S  + (size_t)wid * 16 * S_STRIDE;
    char* eaW = sm + SOFF_EA + (size_t)wid * 16 * EA_STRIDE;
    const uint32_t eaU = smb + SOFF_EA + (uint32_t)wid * 16 * EA_STRIDE;
    const int gq = lid >> 2, t4 = (lid & 3) * 2;
    const uint32_t aAddr = eaU + (uint32_t)((lid & 7) + ((lid >> 3) & 1) * 8) * EA_STRIDE
                         + ((lid >> 4) & 1) * 16;
    const uint32_t b1Off = smb + SOFF_W1C
                         + (uint32_t)((lid & 7) + ((lid >> 4) & 1) * 8) * W1C_STRIDE
                         + ((lid >> 3) & 1) * 16;

    for (int g = blockIdx.x * WPB + wid; g < GROUPS; g += gridDim.x * WPB) {
        const int e0 = g * 16;

        int r = 0, c = 0;
        float dx = 0.f, dy = 0.f, dz = 0.f, dd = 0.f;
        if (lid < 16) {
            r = ei[e0 + lid];
            c = ei[NEDGES + e0 + lid];
            dx = pos[3*r+0] - pos[3*c+0];
            dy = pos[3*r+1] - pos[3*c+1];
            dz = pos[3*r+2] - pos[3*c+2];
            dd = sqrtf(dx*dx + dy*dy + dz*dz);
        }
        __syncwarp();

        // ---- S build (two 8-row passes, champion form) ----
        #pragma unroll
        for (int pass = 0; pass < 2; ++pass) {
            uint2 p1v[8], p2v[8];
            #pragma unroll
            for (int i = 0; i < 8; ++i) {
                int row = pass * 8 + i;
                int ri = __shfl_sync(0xffffffffu, r, row);
                int ci = __shfl_sync(0xffffffffu, c, row);
                p1v[i] = *(const uint2*)(g_P1 + (size_t)ri * HID + 4 * lid);
                p2v[i] = *(const uint2*)(g_P2 + (size_t)ci * HID + 4 * lid);
            }
            #pragma unroll
            for (int i = 0; i < 8; ++i) {
                int row = pass * 8 + i;
                float di = __shfl_sync(0xffffffffu, dd, row);
                __half2 dh = __float2half2_rn(di);
                __half2 sa = __hfma2(dh, w1dA, __hadd2(*(__half2*)&p1v[i].x, *(__half2*)&p2v[i].x));
                __half2 sb = __hfma2(dh, w1dB, __hadd2(*(__half2*)&p1v[i].y, *(__half2*)&p2v[i].y));
                uint2 pk;
                pk.x = *(uint32_t*)&sa; pk.y = *(uint32_t*)&sb;
                *(uint2*)(Sw + row * S_STRIDE + 8 * lid) = pk;
            }
        }
        {
            int erow = lid >> 1, hb = lid & 1;
            const float4* src = (const float4*)(edge_attr + (size_t)(e0 + erow) * 16 + hb * 8);
            float4 u0 = src[0], u1 = src[1];
            __half2 h0 = __floats2half2_rn(u0.x, u0.y), h1 = __floats2half2_rn(u0.z, u0.w);
            __half2 h2 = __floats2half2_rn(u1.x, u1.y), h3 = __floats2half2_rn(u1.z, u1.w);
            uint4 pk;
            pk.x = *(uint32_t*)&h0; pk.y = *(uint32_t*)&h1;
            pk.z = *(uint32_t*)&h2; pk.w = *(uint32_t*)&h3;
            *(uint4*)(eaW + erow * EA_STRIDE + hb * 16) = pk;
        }
        __syncwarp();

        uint32_t a0, a1, a2, a3;
        LDSM_X4(a0, a1, a2, a3, aAddr);

        float acc2[4] = {0.f, 0.f, 0.f, 0.f};
        #pragma unroll
        for (int half = 0; half < 2; ++half) {
            uint32_t bb[4][4];
            #pragma unroll
            for (int j = 0; j < 4; ++j)
                LDSM_X4(bb[j][0], bb[j][1], bb[j][2], bb[j][3],
                        b1Off + (uint32_t)(half * 64 + j * 16) * W1C_STRIDE);
            float acc1[8][4];
            #pragma unroll
            for (int nt = 0; nt < 8; ++nt) { acc1[nt][0]=0.f; acc1[nt][1]=0.f; acc1[nt][2]=0.f; acc1[nt][3]=0.f; }
            #pragma unroll
            for (int j = 0; j < 4; ++j) {
                MMA16816(acc1[2*j][0],acc1[2*j][1],acc1[2*j][2],acc1[2*j][3], a0,a1,a2,a3, bb[j][0], bb[j][1]);
                MMA16816(acc1[2*j+1][0],acc1[2*j+1][1],acc1[2*j+1][2],acc1[2*j+1][3], a0,a1,a2,a3, bb[j][2], bb[j][3]);
            }
            uint32_t hA[8], hB[8];
            #pragma unroll
            for (int nt = 0; nt < 8; ++nt) {
                int colb = (half * 64 + nt * 8 + t4) * 2;
                uint32_t s0 = *(const uint32_t*)(Sw + gq * S_STRIDE + colb);
                uint32_t s1 = *(const uint32_t*)(Sw + (gq + 8) * S_STRIDE + colb);
                __half2 e0h = __floats2half2_rn(acc1[nt][0], acc1[nt][1]);
                __half2 e1h = __floats2half2_rn(acc1[nt][2], acc1[nt][3]);
                __half2 pre0 = __hadd2(e0h, *(__half2*)&s0);
                __half2 pre1 = __hadd2(e1h, *(__half2*)&s1);
                hA[nt] = silu_h2(*(uint32_t*)&pre0);
                hB[nt] = silu_h2(*(uint32_t*)&pre1);
            }
            #pragma unroll
            for (int s2 = 0; s2 < 4; ++s2) {
                int s = half * 4 + s2;
                MMA16816(acc2[0], acc2[1], acc2[2], acc2[3],
                         hA[2*s2], hB[2*s2], hA[2*s2+1], hB[2*s2+1],
                         b2f[s][0], b2f[s][1]);
            }
        }

        int m4 = (lid & 7) * 4;
        float q0 = __shfl_sync(0xffffffffu, acc2[0], m4);
        float q1 = __shfl_sync(0xffffffffu, acc2[1], m4);
        float q2 = __shfl_sync(0xffffffffu, acc2[2], m4);
        float q3 = __shfl_sync(0xffffffffu, acc2[3], m4);
        float r0 = __shfl_sync(0xffffffffu, acc2[0], m4 + 1);
        float r2 = __shfl_sync(0xffffffffu, acc2[2], m4 + 1);
        if (lid < 16) {
            float pw0 = (lid < 8) ? q0 : q2;
            float pw1 = (lid < 8) ? q1 : q3;
            float pw2 = (lid < 8) ? r0 : r2;
            float w0  = silu(pw0 + b20);
            float w1v = silu(pw1 + b21);
            float w2v = silu(pw2 + b22);
            float inv = 1.f / fmaxf(dd, 1e-12f);
            float x = dx * inv, y = dy * inv, z = dz * inv;
            const float s3 = 1.7320508075688772f;
            float* p = g_acc + (size_t)r * 12;
            RED4(p,     w0,                        x * w1v,          y * w1v,                              z * w1v);
            RED4(p + 4, s3 * x * z * w2v,          s3 * x * y * w2v, (y * y - 0.5f * (x * x + z * z)) * w2v, s3 * y * z * w2v);
            RED4(p + 8, 0.5f * s3 * (z * z - x * x) * w2v, 1.0f,     0.f,                                  0.f);
        }
    }
}

// ---------------- launch ----------------
extern "C" void kernel_launch(void* const* d_in, const int* in_sizes, int n_in,
                              void* d_out, int out_size) {
    const float* node_feat = (const float*)d_in[0];
    const float* node_pos  = (const float*)d_in[1];
    const float* edge_attr = (const float*)d_in[2];
    const float* W1        = (const float*)d_in[3];
    const float* b1        = (const float*)d_in[4];
    const float* W2        = (const float*)d_in[5];
    const float* b2        = (const float*)d_in[6];
    const int*   ei        = (const int*)d_in[7];
    float* out = (float*)d_out;

    cudaFuncSetAttribute(prep_P_kernel, cudaFuncAttributeMaxDynamicSharedMemorySize, PP_SMEM);
    cudaFuncSetAttribute(edge_kernel,   cudaFuncAttributeMaxDynamicSharedMemorySize, SMEM_MAIN);

    init_kernel<<<512, 256>>>(W1, W2);
    prep_P_kernel<<<152, 512, PP_SMEM>>>(node_feat, b1);
    edge_kernel<<<152, THREADS, SMEM_MAIN>>>(node_pos, edge_attr, b2, ei);
    finalize_kernel<<<(NNODES + 255) / 256, 256>>>(out);
}